// round 11
// baseline (speedup 1.0000x reference)
#include <cuda_runtime.h>
#include <cuda_fp16.h>
#include <cstdint>

// dendriticNet fused stepper, GB300 sm_103a — Round 11.
// R9/R10 pipeline, warp decomposition changed to cut smem traffic:
//   4 warps/CTA, each owning a 64x64 warp tile (1(M) x 4(N)); every B
//   fragment is read by exactly ONE warp (was two) -> per-chunk L1 bytes
//   drop ~22% (72KB -> 56KB). 128 threads, __launch_bounds__(128,2),
//   2 CTAs/SM, BK=32 / NBUF=4 / cp.async depth-3 (proven R9 pipeline).
//
// Graph-capture safe: kernel launches only, no allocs, scratch = __device__.

#define B_ROWS   32768
#define HDIM     256
#define BM       64
#define BN       256
#define BK       32
#define NTHREADS 128
#define NBUF     4

// Packed tile sizes (bytes)
#define A_BYTES  4096            // 64 x 32 halves, A-fragment order
#define B_BYTES  20480           // 256 x 32 halves, B-fragment order, 80B/lane
#define W_PACK_BYTES (8 * B_BYTES)   // 8 K-chunks per weight
#define SMEM_BYTES (NBUF * (A_BYTES + B_BYTES))   // 98304 per CTA

// Folded constants (DT=0.1, GLK=0.1, GB=1.0, GA=0.8, GD=1.0, GSOM=0.8)
#define ALPHA_S   0.81f
#define ALPHA_S2  0.89f
#define ALPHA_I   0.81f
#define C_B       0.10f
#define C_A       0.08f
#define C_D       0.10f
#define C_SOM     0.08f

#define PREP_THREADS  512
#define PREP_W_BLOCKS 144        // 9*256*32 four-granule tasks / 512

__device__ __align__(16) unsigned char g_wpack[9][W_PACK_BYTES];

// ---------------------------------------------------------------------------
// helpers
// ---------------------------------------------------------------------------
__device__ __forceinline__ uint32_t smem_u32(const void* p) {
    uint32_t a;
    asm("{ .reg .u64 t; cvta.to.shared.u64 t, %1; cvt.u32.u64 %0, t; }" : "=r"(a) : "l"(p));
    return a;
}
__device__ __forceinline__ float tanh_hw(float x) {
    float y;
    asm("tanh.approx.f32 %0, %1;" : "=f"(y) : "f"(x));
    return y;
}
__device__ __forceinline__ void cp_async16(uint32_t saddr, const void* g) {
    asm volatile("cp.async.cg.shared.global [%0], [%1], 16;\n" :: "r"(saddr), "l"(g));
}
__device__ __forceinline__ void cp_commit() { asm volatile("cp.async.commit_group;\n"); }
__device__ __forceinline__ void cp_wait2()  { asm volatile("cp.async.wait_group 2;\n"); }

__device__ __forceinline__ void lds128(uint32_t* r, uint32_t a) {
    asm volatile("ld.shared.v4.b32 {%0,%1,%2,%3}, [%4];"
        : "=r"(r[0]), "=r"(r[1]), "=r"(r[2]), "=r"(r[3]) : "r"(a));
}
__device__ __forceinline__ void sts32(uint32_t a, uint32_t v) {
    asm volatile("st.shared.b32 [%0], %1;" :: "r"(a), "r"(v) : "memory");
}
__device__ __forceinline__ void mma_f16(float c[4], const uint32_t a[4], const uint32_t b[2]) {
    asm volatile(
        "mma.sync.aligned.m16n8k16.row.col.f32.f16.f16.f32 "
        "{%0,%1,%2,%3}, {%4,%5,%6,%7}, {%8,%9}, {%0,%1,%2,%3};\n"
        : "+f"(c[0]), "+f"(c[1]), "+f"(c[2]), "+f"(c[3])
        : "r"(a[0]), "r"(a[1]), "r"(a[2]), "r"(a[3]), "r"(b[0]), "r"(b[1]));
}
__device__ __forceinline__ uint32_t h2bits(float x, float y) {
    __half2 h = __floats2half2_rn(x, y);
    return *reinterpret_cast<uint32_t*>(&h);
}

// ---------------------------------------------------------------------------
// Kernel P: weights -> coef*fp16, B-fragment order (weights only).
// ---------------------------------------------------------------------------
__global__ __launch_bounds__(PREP_THREADS)
void prep_kernel(const float* __restrict__ wpf0, const float* __restrict__ wpi0,
                 const float* __restrict__ wpb0, const float* __restrict__ wpf1,
                 const float* __restrict__ wpi1, const float* __restrict__ wpb1,
                 const float* __restrict__ wpf2, const float* __restrict__ wip0,
                 const float* __restrict__ wip1) {
    const float* Ws[9] = {wpf0, wpi0, wpb0, wpf1, wpi1, wpb1, wpf2, wip0, wip1};
    const float  Cs[9] = {C_B, C_A, C_A, C_B, C_A, C_A, C_B, C_D, C_D};
    int task = blockIdx.x * PREP_THREADS + threadIdx.x;  // < 73728
    int w    = task >> 13;
    int r    = task & 8191;
    int n    = r >> 5;
    int j    = r & 31;
    int k0   = j * 8;

    float cf = Cs[w];
    const float* src = Ws[w] + n * HDIM + k0;
    float4 v01 = *(const float4*)(src);
    float4 v23 = *(const float4*)(src + 4);
    uint32_t g0 = h2bits(cf * v01.x, cf * v01.y);
    uint32_t g1 = h2bits(cf * v01.z, cf * v01.w);
    uint32_t g2 = h2bits(cf * v23.x, cf * v23.y);
    uint32_t g3 = h2bits(cf * v23.z, cf * v23.w);

    int chunk = k0 >> 5;
    int ck    = k0 & 31;
    int kstep = ck >> 4;
    int khi   = ((ck & 15) >= 8) ? 1 : 0;
    int ng    = n >> 6;
    int nn    = n & 63;
    int i     = (nn >> 3) * 2 + khi;
    int lane0 = (nn & 7) * 4;
    uint32_t base = (uint32_t)chunk * B_BYTES + (uint32_t)(ng * 2 + kstep) * 2560
                  + (uint32_t)i * 4;
    unsigned char* dst = g_wpack[w];
    *(uint32_t*)(dst + base + (uint32_t)(lane0 + 0) * 80) = g0;
    *(uint32_t*)(dst + base + (uint32_t)(lane0 + 1) * 80) = g1;
    *(uint32_t*)(dst + base + (uint32_t)(lane0 + 2) * 80) = g2;
    *(uint32_t*)(dst + base + (uint32_t)(lane0 + 3) * 80) = g3;
}

// ---------------------------------------------------------------------------
// Kernel 2: fused fp16 GEMM + epilogue. 128 threads, 4 warps, each warp a
// 64x64 tile (all M rows x its 64-col n-group). CTA tile 64x256. 2 CTAs/SM.
// ---------------------------------------------------------------------------
__global__ __launch_bounds__(NTHREADS, 2)
void fused_kernel(const float* __restrict__ data,
                  const float* __restrict__ s0, const float* __restrict__ s1,
                  const float* __restrict__ s2, const float* __restrict__ i0,
                  const float* __restrict__ i1,
                  float* __restrict__ out) {
    extern __shared__ float smem[];
    uint32_t aBase = smem_u32(smem);                 // NBUF * A_BYTES
    uint32_t bBase = aBase + NBUF * A_BYTES;         // NBUF * B_BYTES

    int bid    = blockIdx.x;
    int out_id = bid % 5;
    int row0   = (bid / 5) * BM;

    const float *A0, *A1 = nullptr, *A2 = nullptr;
    const unsigned char *P0, *P1 = nullptr, *P2 = nullptr;
    int   nterms;
    float alpha;
    const float* ndgsrc = nullptr;    // in-CTA nudge source (s1 or s2)
    const float* st;

    switch (out_id) {
    case 0: nterms = 3; alpha = ALPHA_S;  st = s0;
            A0 = data; P0 = g_wpack[0];
            A1 = i0;   P1 = g_wpack[1];
            A2 = s1;   P2 = g_wpack[2];  break;
    case 1: nterms = 3; alpha = ALPHA_S;  st = s1;
            A0 = s0;   P0 = g_wpack[3];
            A1 = i1;   P1 = g_wpack[4];
            A2 = s2;   P2 = g_wpack[5];  break;
    case 2: nterms = 1; alpha = ALPHA_S2; st = s2;
            A0 = s1;   P0 = g_wpack[6];  break;
    case 3: nterms = 1; alpha = ALPHA_I;  st = i0; ndgsrc = s1;
            A0 = s0;   P0 = g_wpack[7];  break;
    default:nterms = 1; alpha = ALPHA_I;  st = i1; ndgsrc = s2;
            A0 = s1;   P0 = g_wpack[8];  break;
    }
    const int NCH = nterms * (HDIM / BK);   // 8 or 24

    int tid  = threadIdx.x;
    int lane = tid & 31;
    int warp = tid >> 5;
    int qr   = lane >> 2;
    int qc   = lane & 3;
    int ngrp = warp;                   // B n-group (64 cols), one per warp

    float acc[4][8][4];                // 128 fp32 accumulators (64x64 tile)
    #pragma unroll
    for (int mt = 0; mt < 4; mt++)
        #pragma unroll
        for (int nt = 0; nt < 8; nt++)
            #pragma unroll
            for (int kx = 0; kx < 4; kx++) acc[mt][nt][kx] = 0.f;

    // ---- A staging: 512 float4-tasks (64 rows x 8 segs), 4 per thread ----
    int arb = tid >> 3;        // rows arb, arb+16, arb+32, arb+48
    int seg = tid & 7;         // float4 index within 32-float row-chunk

    auto aoff = [&](int r, int ckg) -> uint32_t {
        int kstep = ckg >> 4;
        int ww    = ckg & 15;
        int tig   = (ww >> 1) & 3;
        int khi   = (ww >= 8) ? 1 : 0;
        int gi    = (khi << 1) | ((r >> 3) & 1);
        int ln    = (r & 7) * 4 + tig;
        return (uint32_t)(((r >> 4) * 2 + kstep) * 512 + ln * 16 + gi * 4);
    };
    uint32_t ao[4][2];
    #pragma unroll
    for (int k = 0; k < 4; k++) {
        ao[k][0] = aoff(arb + 16 * k, seg * 4);
        ao[k][1] = aoff(arb + 16 * k, seg * 4 + 2);
    }

    float4 ra[4];

    auto loadA = [&](int c) {
        int t  = c >> 3;
        int k0 = (c & 7) * BK;
        const float* A = (t == 0) ? A0 : ((t == 1) ? A1 : A2);
        #pragma unroll
        for (int k = 0; k < 4; k++)
            ra[k] = *(const float4*)(A + (size_t)(row0 + arb + 16 * k) * HDIM
                                     + k0 + seg * 4);
    };
    auto storeA = [&](int c) {
        uint32_t base = aBase + (uint32_t)(c & (NBUF - 1)) * A_BYTES;
        #pragma unroll
        for (int k = 0; k < 4; k++) {
            sts32(base + ao[k][0], h2bits(tanh_hw(ra[k].x), tanh_hw(ra[k].y)));
            sts32(base + ao[k][1], h2bits(tanh_hw(ra[k].z), tanh_hw(ra[k].w)));
        }
    };

    // ---- B staging: identity cp.async, 1280 x 16B tasks, 10 per thread ----
    auto loadB = [&](int c) {
        int t = c >> 3;
        const unsigned char* src =
            ((t == 0) ? P0 : ((t == 1) ? P1 : P2)) + (size_t)(c & 7) * B_BYTES;
        uint32_t dst = bBase + (uint32_t)(c & (NBUF - 1)) * B_BYTES;
        #pragma unroll
        for (int j = 0; j < 10; j++) {
            int tsk = tid + j * NTHREADS;
            cp_async16(dst + (uint32_t)tsk * 16, src + (size_t)tsk * 16);
        }
    };

    auto compute = [&](int c) {
        uint32_t aB = aBase + (uint32_t)(c & (NBUF - 1)) * A_BYTES;
        uint32_t bB = bBase + (uint32_t)(c & (NBUF - 1)) * B_BYTES;
        #pragma unroll
        for (int ks = 0; ks < 2; ks++) {
            uint32_t af[4][4], bf[16];
            #pragma unroll
            for (int mt = 0; mt < 4; mt++)
                lds128(af[mt], aB + (uint32_t)((mt * 2 + ks) * 512 + lane * 16));
            uint32_t bb = bB + (uint32_t)((ngrp * 2 + ks) * 2560 + lane * 80);
            lds128(bf + 0,  bb);
            lds128(bf + 4,  bb + 16);
            lds128(bf + 8,  bb + 32);
            lds128(bf + 12, bb + 48);
            #pragma unroll
            for (int nt = 0; nt < 8; nt++)
                #pragma unroll
                for (int mt = 0; mt < 4; mt++)
                    mma_f16(acc[mt][nt], af[mt], bf + nt * 2);
        }
    };

    // ---- pipeline (identical structure to R9) ----
    loadB(0); cp_commit();
    loadB(1); cp_commit();
    loadB(2); cp_commit();
    loadA(0);
    storeA(0);
    loadA(1);
    cp_wait2();              // B chunk 0 done
    __syncthreads();         // chunk 0 visible

    for (int c = 0; c < NCH; c++) {
        if (c + 1 < NCH) storeA(c + 1);     // buf (c+1)%4: compute(c-3) done+synced
        if (c + 2 < NCH) loadA(c + 2);      // consumed a full compute later
        if (c + 3 < NCH) loadB(c + 3);      // buf (c-1)%4: done+synced
        cp_commit();
        compute(c);
        cp_wait2();                         // B chunk c+1 done
        __syncthreads();                    // chunk c+1 visible
    }

    // ---- in-CTA nudge (out3/out4): 64 row means of tanh(src) ----
    float* nsm = smem;                      // smem dead after final barrier
    if (ndgsrc) {
        int rbase = warp * 16;
        #pragma unroll
        for (int rr = 0; rr < 16; rr++) {
            int row = row0 + rbase + rr;
            const float4* p = (const float4*)(ndgsrc + (size_t)row * HDIM) + lane * 2;
            float4 v = p[0], u = p[1];
            float s = tanh_hw(v.x) + tanh_hw(v.y) + tanh_hw(v.z) + tanh_hw(v.w)
                    + tanh_hw(u.x) + tanh_hw(u.y) + tanh_hw(u.z) + tanh_hw(u.w);
            #pragma unroll
            for (int o = 16; o; o >>= 1) s += __shfl_xor_sync(0xffffffffu, s, o);
            if (lane == 0) nsm[rbase + rr] = s * (C_SOM / (float)HDIM);
        }
        __syncthreads();
    }

    // ---- epilogue: out = alpha*state + acc (+ nudge for i-outputs) ----
    size_t obase = (size_t)out_id * B_ROWS * HDIM;
    int n0 = ngrp * 64;
    #pragma unroll
    for (int mt = 0; mt < 4; mt++) {
        #pragma unroll
        for (int half = 0; half < 2; half++) {
            int rr  = mt * 16 + qr + half * 8;
            int row = row0 + rr;
            float nv = ndgsrc ? nsm[rr] : 0.f;
            const float* sp = st + (size_t)row * HDIM + n0;
            float*       op = out + obase + (size_t)row * HDIM + n0;
            #pragma unroll
            for (int nt = 0; nt < 8; nt++) {
                int cc = nt * 8 + 2 * qc;
                float2 sv = *(const float2*)(sp + cc);
                float v0 = alpha * sv.x + acc[mt][nt][half * 2 + 0] + nv;
                float v1 = alpha * sv.y + acc[mt][nt][half * 2 + 1] + nv;
                *(float2*)(op + cc) = make_float2(v0, v1);
            }
        }
    }
}

// ---------------------------------------------------------------------------
extern "C" void kernel_launch(void* const* d_in, const int* in_sizes, int n_in,
                              void* d_out, int out_size) {
    const float* data = (const float*)d_in[0];
    const float* s0   = (const float*)d_in[1];
    const float* s1   = (const float*)d_in[2];
    const float* s2   = (const float*)d_in[3];
    const float* i0   = (const float*)d_in[4];
    const float* i1   = (const float*)d_in[5];
    const float* wpf0 = (const float*)d_in[6];
    const float* wpf1 = (const float*)d_in[7];
    const float* wpf2 = (const float*)d_in[8];
    const float* wpb0 = (const float*)d_in[9];
    const float* wpb1 = (const float*)d_in[10];
    const float* wip0 = (const float*)d_in[11];
    const float* wip1 = (const float*)d_in[12];
    const float* wpi0 = (const float*)d_in[13];
    const float* wpi1 = (const float*)d_in[14];
    float* out = (float*)d_out;

    cudaFuncSetAttribute(fused_kernel,
                         cudaFuncAttributeMaxDynamicSharedMemorySize, SMEM_BYTES);

    // weights-only prep (coef folded into fp16 pack)
    prep_kernel<<<PREP_W_BLOCKS, PREP_THREADS>>>(
        wpf0, wpi0, wpb0, wpf1, wpi1, wpb1, wpf2, wip0, wip1);

    // 5 outputs x 512 row tiles = 2560 CTAs; adjacent bids = different outputs
    // on the same rows -> L2 reuse of activations.
    fused_kernel<<<2560, NTHREADS, SMEM_BYTES>>>(data, s0, s1, s2, i0, i1, out);
}

// round 13
// speedup vs baseline: 1.4314x; 1.4314x over previous
#include <cuda_runtime.h>
#include <cuda_fp16.h>
#include <cstdint>

// dendriticNet fused stepper, GB300 sm_103a — Round 12 (consolidation).
// Fused kernel = R9 exactly (best measured: 164.2us fused): 256 threads,
// BM=64 x BN=256, BK=32, NBUF=4, cp.async depth-3, warps 2(M)x4(N),
// __launch_bounds__(256,2) -> 2 CTAs/SM.
// Plus R10's independently-good pieces: weights-only prep (~4us) and
// in-CTA nudge for out3/out4 (no serialized nudge pass).
//
// Graph-capture safe: kernel launches only, no allocs, scratch = __device__.

#define B_ROWS   32768
#define HDIM     256
#define BM       64
#define BN       256
#define BK       32
#define NTHREADS 256
#define NBUF     4

// Packed tile sizes (bytes)
#define A_BYTES  4096            // 64 x 32 halves, A-fragment order
#define B_BYTES  20480           // 256 x 32 halves, B-fragment order, 80B/lane
#define W_PACK_BYTES (8 * B_BYTES)   // 8 K-chunks per weight
#define SMEM_BYTES (NBUF * (A_BYTES + B_BYTES))   // 98304 per CTA

// Folded constants (DT=0.1, GLK=0.1, GB=1.0, GA=0.8, GD=1.0, GSOM=0.8)
#define ALPHA_S   0.81f
#define ALPHA_S2  0.89f
#define ALPHA_I   0.81f
#define C_B       0.10f
#define C_A       0.08f
#define C_D       0.10f
#define C_SOM     0.08f

#define PREP_THREADS  512
#define PREP_W_BLOCKS 144        // 9*256*32 four-granule tasks / 512

__device__ __align__(16) unsigned char g_wpack[9][W_PACK_BYTES];

// ---------------------------------------------------------------------------
// helpers
// ---------------------------------------------------------------------------
__device__ __forceinline__ uint32_t smem_u32(const void* p) {
    uint32_t a;
    asm("{ .reg .u64 t; cvta.to.shared.u64 t, %1; cvt.u32.u64 %0, t; }" : "=r"(a) : "l"(p));
    return a;
}
__device__ __forceinline__ float tanh_hw(float x) {
    float y;
    asm("tanh.approx.f32 %0, %1;" : "=f"(y) : "f"(x));
    return y;
}
__device__ __forceinline__ void cp_async16(uint32_t saddr, const void* g) {
    asm volatile("cp.async.cg.shared.global [%0], [%1], 16;\n" :: "r"(saddr), "l"(g));
}
__device__ __forceinline__ void cp_commit() { asm volatile("cp.async.commit_group;\n"); }
__device__ __forceinline__ void cp_wait2()  { asm volatile("cp.async.wait_group 2;\n"); }

__device__ __forceinline__ void lds128(uint32_t* r, uint32_t a) {
    asm volatile("ld.shared.v4.b32 {%0,%1,%2,%3}, [%4];"
        : "=r"(r[0]), "=r"(r[1]), "=r"(r[2]), "=r"(r[3]) : "r"(a));
}
__device__ __forceinline__ void sts32(uint32_t a, uint32_t v) {
    asm volatile("st.shared.b32 [%0], %1;" :: "r"(a), "r"(v) : "memory");
}
__device__ __forceinline__ void mma_f16(float c[4], const uint32_t a[4], const uint32_t b[2]) {
    asm volatile(
        "mma.sync.aligned.m16n8k16.row.col.f32.f16.f16.f32 "
        "{%0,%1,%2,%3}, {%4,%5,%6,%7}, {%8,%9}, {%0,%1,%2,%3};\n"
        : "+f"(c[0]), "+f"(c[1]), "+f"(c[2]), "+f"(c[3])
        : "r"(a[0]), "r"(a[1]), "r"(a[2]), "r"(a[3]), "r"(b[0]), "r"(b[1]));
}
__device__ __forceinline__ uint32_t h2bits(float x, float y) {
    __half2 h = __floats2half2_rn(x, y);
    return *reinterpret_cast<uint32_t*>(&h);
}

// ---------------------------------------------------------------------------
// Kernel P: weights -> coef*fp16, B-fragment order (weights only).
// ---------------------------------------------------------------------------
__global__ __launch_bounds__(PREP_THREADS)
void prep_kernel(const float* __restrict__ wpf0, const float* __restrict__ wpi0,
                 const float* __restrict__ wpb0, const float* __restrict__ wpf1,
                 const float* __restrict__ wpi1, const float* __restrict__ wpb1,
                 const float* __restrict__ wpf2, const float* __restrict__ wip0,
                 const float* __restrict__ wip1) {
    const float* Ws[9] = {wpf0, wpi0, wpb0, wpf1, wpi1, wpb1, wpf2, wip0, wip1};
    const float  Cs[9] = {C_B, C_A, C_A, C_B, C_A, C_A, C_B, C_D, C_D};
    int task = blockIdx.x * PREP_THREADS + threadIdx.x;  // < 73728
    int w    = task >> 13;
    int r    = task & 8191;
    int n    = r >> 5;
    int j    = r & 31;
    int k0   = j * 8;

    float cf = Cs[w];
    const float* src = Ws[w] + n * HDIM + k0;
    float4 v01 = *(const float4*)(src);
    float4 v23 = *(const float4*)(src + 4);
    uint32_t g0 = h2bits(cf * v01.x, cf * v01.y);
    uint32_t g1 = h2bits(cf * v01.z, cf * v01.w);
    uint32_t g2 = h2bits(cf * v23.x, cf * v23.y);
    uint32_t g3 = h2bits(cf * v23.z, cf * v23.w);

    int chunk = k0 >> 5;
    int ck    = k0 & 31;
    int kstep = ck >> 4;
    int khi   = ((ck & 15) >= 8) ? 1 : 0;
    int ng    = n >> 6;
    int nn    = n & 63;
    int i     = (nn >> 3) * 2 + khi;
    int lane0 = (nn & 7) * 4;
    uint32_t base = (uint32_t)chunk * B_BYTES + (uint32_t)(ng * 2 + kstep) * 2560
                  + (uint32_t)i * 4;
    unsigned char* dst = g_wpack[w];
    *(uint32_t*)(dst + base + (uint32_t)(lane0 + 0) * 80) = g0;
    *(uint32_t*)(dst + base + (uint32_t)(lane0 + 1) * 80) = g1;
    *(uint32_t*)(dst + base + (uint32_t)(lane0 + 2) * 80) = g2;
    *(uint32_t*)(dst + base + (uint32_t)(lane0 + 3) * 80) = g3;
}

// ---------------------------------------------------------------------------
// Kernel 2: fused fp16 GEMM + epilogue. 256 threads, 8 warps 2(M)x4(N),
// warp tile 32x64, CTA tile 64x256. Two CTAs per SM. (R9 verbatim.)
// ---------------------------------------------------------------------------
__global__ __launch_bounds__(NTHREADS, 2)
void fused_kernel(const float* __restrict__ data,
                  const float* __restrict__ s0, const float* __restrict__ s1,
                  const float* __restrict__ s2, const float* __restrict__ i0,
                  const float* __restrict__ i1,
                  float* __restrict__ out) {
    extern __shared__ float smem[];
    uint32_t aBase = smem_u32(smem);                 // NBUF * A_BYTES
    uint32_t bBase = aBase + NBUF * A_BYTES;         // NBUF * B_BYTES

    int bid    = blockIdx.x;
    int out_id = bid % 5;
    int row0   = (bid / 5) * BM;

    const float *A0, *A1 = nullptr, *A2 = nullptr;
    const unsigned char *P0, *P1 = nullptr, *P2 = nullptr;
    int   nterms;
    float alpha;
    const float* ndgsrc = nullptr;    // in-CTA nudge source (s1 or s2)
    const float* st;

    switch (out_id) {
    case 0: nterms = 3; alpha = ALPHA_S;  st = s0;
            A0 = data; P0 = g_wpack[0];
            A1 = i0;   P1 = g_wpack[1];
            A2 = s1;   P2 = g_wpack[2];  break;
    case 1: nterms = 3; alpha = ALPHA_S;  st = s1;
            A0 = s0;   P0 = g_wpack[3];
            A1 = i1;   P1 = g_wpack[4];
            A2 = s2;   P2 = g_wpack[5];  break;
    case 2: nterms = 1; alpha = ALPHA_S2; st = s2;
            A0 = s1;   P0 = g_wpack[6];  break;
    case 3: nterms = 1; alpha = ALPHA_I;  st = i0; ndgsrc = s1;
            A0 = s0;   P0 = g_wpack[7];  break;
    default:nterms = 1; alpha = ALPHA_I;  st = i1; ndgsrc = s2;
            A0 = s1;   P0 = g_wpack[8];  break;
    }
    const int NCH = nterms * (HDIM / BK);   // 8 or 24

    int tid  = threadIdx.x;
    int lane = tid & 31;
    int warp = tid >> 5;
    int qr   = lane >> 2;
    int qc   = lane & 3;
    int mtb  = (warp >> 2) * 2;        // A m16-tile base (0 or 2)
    int ngrp = warp & 3;               // B n-group (64 cols)

    float acc[2][8][4];
    #pragma unroll
    for (int mt = 0; mt < 2; mt++)
        #pragma unroll
        for (int nt = 0; nt < 8; nt++)
            #pragma unroll
            for (int kx = 0; kx < 4; kx++) acc[mt][nt][kx] = 0.f;

    // ---- A staging: 512 float4-tasks (64 rows x 8 segs), 2 per thread ----
    int ar0 = tid >> 3;        // rows 0..31
    int seg = tid & 7;         // float4 index within 32-float row-chunk
    int ar1 = ar0 + 32;        // rows 32..63

    auto aoff = [&](int r, int ckg) -> uint32_t {
        int kstep = ckg >> 4;
        int ww    = ckg & 15;
        int tig   = (ww >> 1) & 3;
        int khi   = (ww >= 8) ? 1 : 0;
        int gi    = (khi << 1) | ((r >> 3) & 1);
        int ln    = (r & 7) * 4 + tig;
        return (uint32_t)(((r >> 4) * 2 + kstep) * 512 + ln * 16 + gi * 4);
    };
    uint32_t ao00 = aoff(ar0, seg * 4);
    uint32_t ao01 = aoff(ar0, seg * 4 + 2);
    uint32_t ao10 = aoff(ar1, seg * 4);
    uint32_t ao11 = aoff(ar1, seg * 4 + 2);

    float4 ra0, ra1;

    auto loadA = [&](int c) {
        int t  = c >> 3;
        int k0 = (c & 7) * BK;
        const float* A = (t == 0) ? A0 : ((t == 1) ? A1 : A2);
        ra0 = *(const float4*)(A + (size_t)(row0 + ar0) * HDIM + k0 + seg * 4);
        ra1 = *(const float4*)(A + (size_t)(row0 + ar1) * HDIM + k0 + seg * 4);
    };
    auto storeA = [&](int c) {
        uint32_t base = aBase + (uint32_t)(c & (NBUF - 1)) * A_BYTES;
        sts32(base + ao00, h2bits(tanh_hw(ra0.x), tanh_hw(ra0.y)));
        sts32(base + ao01, h2bits(tanh_hw(ra0.z), tanh_hw(ra0.w)));
        sts32(base + ao10, h2bits(tanh_hw(ra1.x), tanh_hw(ra1.y)));
        sts32(base + ao11, h2bits(tanh_hw(ra1.z), tanh_hw(ra1.w)));
    };

    // ---- B staging: identity cp.async, 1280 x 16B tasks, 5 per thread ----
    auto loadB = [&](int c) {
        int t = c >> 3;
        const unsigned char* src =
            ((t == 0) ? P0 : ((t == 1) ? P1 : P2)) + (size_t)(c & 7) * B_BYTES;
        uint32_t dst = bBase + (uint32_t)(c & (NBUF - 1)) * B_BYTES;
        #pragma unroll
        for (int j = 0; j < 5; j++) {
            int tsk = tid + j * NTHREADS;
            cp_async16(dst + (uint32_t)tsk * 16, src + (size_t)tsk * 16);
        }
    };

    auto compute = [&](int c) {
        uint32_t aB = aBase + (uint32_t)(c & (NBUF - 1)) * A_BYTES;
        uint32_t bB = bBase + (uint32_t)(c & (NBUF - 1)) * B_BYTES;
        #pragma unroll
        for (int ks = 0; ks < 2; ks++) {
            uint32_t af[2][4], bf[16];
            lds128(af[0], aB + (uint32_t)(((mtb + 0) * 2 + ks) * 512 + lane * 16));
            lds128(af[1], aB + (uint32_t)(((mtb + 1) * 2 + ks) * 512 + lane * 16));
            uint32_t bb = bB + (uint32_t)((ngrp * 2 + ks) * 2560 + lane * 80);
            lds128(bf + 0,  bb);
            lds128(bf + 4,  bb + 16);
            lds128(bf + 8,  bb + 32);
            lds128(bf + 12, bb + 48);
            #pragma unroll
            for (int nt = 0; nt < 8; nt++) {
                mma_f16(acc[0][nt], af[0], bf + nt * 2);
                mma_f16(acc[1][nt], af[1], bf + nt * 2);
            }
        }
    };

    // ---- pipeline (R9 verbatim) ----
    loadB(0); cp_commit();
    loadB(1); cp_commit();
    loadB(2); cp_commit();
    loadA(0);
    storeA(0);
    loadA(1);
    cp_wait2();              // B chunk 0 done
    __syncthreads();         // chunk 0 visible

    for (int c = 0; c < NCH; c++) {
        if (c + 1 < NCH) storeA(c + 1);     // buf (c+1)%4: compute(c-3) done+synced
        if (c + 2 < NCH) loadA(c + 2);      // full compute of cover before its store
        if (c + 3 < NCH) loadB(c + 3);      // buf (c-1)%4: done+synced
        cp_commit();
        compute(c);
        cp_wait2();                         // B chunk c+1 done
        __syncthreads();                    // chunk c+1 visible
    }

    // ---- in-CTA nudge (out3/out4): 64 row means of tanh(src) ----
    // smem data buffers are dead after the final barrier; reuse for nudge[64].
    float* nsm = smem;
    if (ndgsrc) {
        int rbase = warp * 8;
        #pragma unroll
        for (int rr = 0; rr < 8; rr++) {
            int row = row0 + rbase + rr;
            const float4* p = (const float4*)(ndgsrc + (size_t)row * HDIM) + lane * 2;
            float4 v = p[0], u = p[1];
            float s = tanh_hw(v.x) + tanh_hw(v.y) + tanh_hw(v.z) + tanh_hw(v.w)
                    + tanh_hw(u.x) + tanh_hw(u.y) + tanh_hw(u.z) + tanh_hw(u.w);
            #pragma unroll
            for (int o = 16; o; o >>= 1) s += __shfl_xor_sync(0xffffffffu, s, o);
            if (lane == 0) nsm[rbase + rr] = s * (C_SOM / (float)HDIM);
        }
        __syncthreads();
    }

    // ---- epilogue: out = alpha*state + acc (+ nudge for i-outputs) ----
    size_t obase = (size_t)out_id * B_ROWS * HDIM;
    int m0 = (warp >> 2) * 32;
    int n0 = ngrp * 64;
    #pragma unroll
    for (int mt = 0; mt < 2; mt++) {
        #pragma unroll
        for (int half = 0; half < 2; half++) {
            int rr  = m0 + mt * 16 + qr + half * 8;
            int row = row0 + rr;
            float nv = ndgsrc ? nsm[rr] : 0.f;
            const float* sp = st + (size_t)row * HDIM + n0;
            float*       op = out + obase + (size_t)row * HDIM + n0;
            #pragma unroll
            for (int nt = 0; nt < 8; nt++) {
                int cc = nt * 8 + 2 * qc;
                float2 sv = *(const float2*)(sp + cc);
                float v0 = alpha * sv.x + acc[mt][nt][half * 2 + 0] + nv;
                float v1 = alpha * sv.y + acc[mt][nt][half * 2 + 1] + nv;
                *(float2*)(op + cc) = make_float2(v0, v1);
            }
        }
    }
}

// ---------------------------------------------------------------------------
extern "C" void kernel_launch(void* const* d_in, const int* in_sizes, int n_in,
                              void* d_out, int out_size) {
    const float* data = (const float*)d_in[0];
    const float* s0   = (const float*)d_in[1];
    const float* s1   = (const float*)d_in[2];
    const float* s2   = (const float*)d_in[3];
    const float* i0   = (const float*)d_in[4];
    const float* i1   = (const float*)d_in[5];
    const float* wpf0 = (const float*)d_in[6];
    const float* wpf1 = (const float*)d_in[7];
    const float* wpf2 = (const float*)d_in[8];
    const float* wpb0 = (const float*)d_in[9];
    const float* wpb1 = (const float*)d_in[10];
    const float* wip0 = (const float*)d_in[11];
    const float* wip1 = (const float*)d_in[12];
    const float* wpi0 = (const float*)d_in[13];
    const float* wpi1 = (const float*)d_in[14];
    float* out = (float*)d_out;

    cudaFuncSetAttribute(fused_kernel,
                         cudaFuncAttributeMaxDynamicSharedMemorySize, SMEM_BYTES);

    // weights-only prep (coef folded into fp16 pack)
    prep_kernel<<<PREP_W_BLOCKS, PREP_THREADS>>>(
        wpf0, wpi0, wpb0, wpf1, wpi1, wpb1, wpf2, wip0, wip1);

    // 5 outputs x 512 row tiles = 2560 CTAs; adjacent bids = different outputs
    // on the same rows -> L2 reuse of activations.
    fused_kernel<<<2560, NTHREADS, SMEM_BYTES>>>(data, s0, s1, s2, i0, i1, out);
}